// round 12
// baseline (speedup 1.0000x reference)
#include <cuda_runtime.h>
#include <stdint.h>

#define N        100800
#define NC       80
#define STRIDE   85
#define MAX_NMS  4096
#define MAX_DET  1000
#define CAP      16384
#define NB       256
#define KBASE    0x3ECCu
#define CONF_T   0.4f
#define IOU_T    0.45f
#define MAX_WH   7680.0f
#define ECAP     4096
#define NTILE    2080           // 64*65/2 upper-tri 64x64 tiles

typedef unsigned long long u64;

// ---------------- scratch (static __device__, allocation-free) ----------------
__device__ unsigned int g_hist[NB];     // zeroed at tail of final block
__device__ unsigned int g_boff[NB];
__device__ unsigned int g_bcnt[NB];
__device__ unsigned int g_key[N];
__device__ unsigned int g_cutoff, g_total, g_bmax;
__device__ unsigned int g_ecnt = 0;     // zeroed at tail of final block
__device__ unsigned int g_done = 0;     // last-block election counter
__device__ u64          g_cand[CAP];
__device__ float4       g_obox[MAX_NMS];
__device__ float        g_area[MAX_NMS];
__device__ float4       g_bbox[MAX_NMS];
__device__ float        g_score[MAX_NMS];
__device__ float        g_clsf[MAX_NMS];
__device__ unsigned int g_edge[ECAP];

// ---------------- K1: warp-per-anchor score (obj-skip + redux) ----------------
__global__ void k_scores(const float* __restrict__ pred) {
    int a    = (blockIdx.x * blockDim.x + threadIdx.x) >> 5;
    int lane = threadIdx.x & 31;
    if (a >= N) return;
    const float* r = pred + (size_t)a * STRIDE;
    float v0 = r[lane];                              // obj + cls[0..26]
    float obj = __shfl_sync(0xffffffffu, v0, 4);
    unsigned int key = 0u;
    if (obj > CONF_T) {                              // else conf <= obj <= 0.4
        float v1 = r[lane + 32];
        float v2 = (lane < 21) ? r[lane + 64] : 0.0f;
        float m = 0.0f;
        if (lane >= 5) m = __fmul_rn(v0, obj);
        m = fmaxf(m, __fmul_rn(v1, obj));
        if (lane < 21) m = fmaxf(m, __fmul_rn(v2, obj));
        // all lane values >= 0 -> float bits monotone
        unsigned int mu = __reduce_max_sync(0xffffffffu, __float_as_uint(m));
        if (__uint_as_float(mu) > CONF_T) key = mu;
    }
    if (lane == 0) {
        g_key[a] = key;
        if (key) {
            unsigned int b = (key >> 16) - KBASE;
            if (b > 255u) b = 255u;
            atomicAdd(&g_hist[b], 1u);
        }
    }
}

// ---------------- K2: 256-bucket suffix scan ----------------
__global__ void k_scan() {
    __shared__ unsigned int s[NB];
    __shared__ int sb;
    int t = threadIdx.x;
    unsigned int h = g_hist[t];
    s[t] = h;
    if (t == 0) sb = 0;
    __syncthreads();
    for (int off = 1; off < NB; off <<= 1) {
        unsigned int v = (t + off < NB) ? s[t + off] : 0u;
        __syncthreads();
        s[t] += v;
        __syncthreads();
    }
    g_boff[t] = (t < NB - 1) ? s[t + 1] : 0u;
    g_bcnt[t] = 0u;
    if (s[t] >= (unsigned)MAX_NMS && (t == NB - 1 || s[t + 1] < (unsigned)MAX_NMS)) {
        g_cutoff = (unsigned)t;
        g_total  = s[t];
    }
    if (h) atomicMax(&sb, t);
    __syncthreads();
    if (t == 0) {
        g_bmax = (unsigned)sb;
        if (s[0] < (unsigned)MAX_NMS) { g_cutoff = 0u; g_total = s[0]; }
    }
}

// ---------------- K3: scatter candidates into bucket segments ----------------
__global__ void k_gather() {
    int i = blockIdx.x * blockDim.x + threadIdx.x;
    if (i >= N) return;
    unsigned int key = g_key[i];
    if (!key) return;
    unsigned int b = (key >> 16) - KBASE;
    if (b > 255u) b = 255u;
    if (b < g_cutoff) return;
    unsigned int pos = g_boff[b] + atomicAdd(&g_bcnt[b], 1u);
    if (pos < CAP)
        g_cand[pos] = ((u64)key << 32) | (unsigned int)(~(unsigned int)i);
}

// ---------------- decode one rank ----------------
__device__ __forceinline__ void decode_rank(const float* __restrict__ pred,
                                            u64 key, int r) {
    unsigned int kb  = (unsigned int)(key >> 32);
    unsigned int idx = ~(unsigned int)(key & 0xFFFFFFFFu);
    const float* row = pred + (size_t)idx * STRIDE;
    float x = row[0], y = row[1], w = row[2], h = row[3], obj = row[4];
    float bestv = -1.0f; int bestc = 0;
#pragma unroll 8
    for (int c = 0; c < NC; c++) {
        float p = __fmul_rn(row[5 + c], obj);
        if (p > bestv) { bestv = p; bestc = c; }
    }
    float hw = __fmul_rn(w, 0.5f), hh = __fmul_rn(h, 0.5f);
    float x1 = __fsub_rn(x, hw), y1 = __fsub_rn(y, hh);
    float x2 = __fadd_rn(x, hw), y2 = __fadd_rn(y, hh);
    float cf = (float)bestc;
    float off = __fmul_rn(cf, MAX_WH);
    float ox1 = __fadd_rn(x1, off), oy1 = __fadd_rn(y1, off);
    float ox2 = __fadd_rn(x2, off), oy2 = __fadd_rn(y2, off);
    float area = __fmul_rn(__fsub_rn(ox2, ox1), __fsub_rn(oy2, oy1));
    g_obox[r]  = make_float4(ox1, oy1, ox2, oy2);
    g_area[r]  = area;
    g_bbox[r]  = make_float4(x1, y1, x2, y2);
    g_score[r] = __uint_as_float(kb);
    g_clsf[r]  = cf;
}

// ---------------- K4: per-bucket rank-by-count sort + fused decode ----------
// Rank-by-count kept entirely in scalar registers (no indexable local arrays).
__global__ void k_bsort_decode(const float* __restrict__ pred) {
    __shared__ u64 sbuf[4096];          // 32KB
    const int tid = threadIdx.x;        // 256 threads
    unsigned int cutoff = g_cutoff, bmax = g_bmax;
    unsigned int limit = g_total;
    if (limit > (unsigned)MAX_NMS) limit = MAX_NMS;

    for (unsigned int b = cutoff + blockIdx.x; b <= bmax; b += gridDim.x) {
        unsigned int L = g_hist[b];
        if (L == 0) continue;
        unsigned int off = g_boff[b];
        if (off >= limit) continue;
        if (L > 4096u) L = 4096u;
        if (L == 1) {
            if (tid == 0) decode_rank(pred, g_cand[off], off);
            continue;
        }
        for (unsigned int j = tid; j < L; j += 256) sbuf[j] = g_cand[off + j];
        __syncthreads();
        if (L <= 1024u) {
            // fixed register slots: items tid, tid+256, tid+512, tid+768
            u64 m0 = ((unsigned)tid        < L) ? sbuf[tid]       : ~0ULL;
            u64 m1 = ((unsigned)tid + 256u < L) ? sbuf[tid + 256] : ~0ULL;
            u64 m2 = ((unsigned)tid + 512u < L) ? sbuf[tid + 512] : ~0ULL;
            u64 m3 = ((unsigned)tid + 768u < L) ? sbuf[tid + 768] : ~0ULL;
            unsigned int c0 = 0, c1 = 0, c2 = 0, c3 = 0;
#pragma unroll 4
            for (unsigned int j = 0; j < L; j++) {
                u64 v = sbuf[j];                    // smem broadcast
                c0 += (v > m0); c1 += (v > m1);
                c2 += (v > m2); c3 += (v > m3);
            }
            if ((unsigned)tid < L) {
                unsigned int r = off + c0;
                if (r < limit) decode_rank(pred, m0, (int)r);
            }
            if ((unsigned)tid + 256u < L) {
                unsigned int r = off + c1;
                if (r < limit) decode_rank(pred, m1, (int)r);
            }
            if ((unsigned)tid + 512u < L) {
                unsigned int r = off + c2;
                if (r < limit) decode_rank(pred, m2, (int)r);
            }
            if ((unsigned)tid + 768u < L) {
                unsigned int r = off + c3;
                if (r < limit) decode_rank(pred, m3, (int)r);
            }
        } else {
            // bitonic fallback (rare)
            unsigned int P = 2; while (P < L) P <<= 1;
            for (unsigned int j = L + tid; j < P; j += 256) sbuf[j] = 0ULL;
            __syncthreads();
            for (unsigned int k = 2; k <= P; k <<= 1) {
                for (unsigned int j = k >> 1; j > 0; j >>= 1) {
                    for (unsigned int p = tid; p < P / 2; p += 256) {
                        unsigned int i = ((p & ~(j - 1)) << 1) | (p & (j - 1));
                        u64 a = sbuf[i], c = sbuf[i + j];
                        bool sw = ((i & k) == 0) ? (a < c) : (a > c);
                        if (sw) { sbuf[i] = c; sbuf[i + j] = a; }
                    }
                    __syncthreads();
                }
            }
            for (unsigned int j = tid; j < L; j += 256) {
                unsigned int r = off + j;
                if (r < limit) decode_rank(pred, sbuf[j], (int)r);
            }
        }
        __syncthreads();
    }
}

// ---------------- K5: edges + (last block) greedy + emit + state reset -------
__global__ void k_edges_final(float* __restrict__ out) {
    __shared__ unsigned int se[4096];       // raw edges
    __shared__ unsigned int se2[4096];      // rank-sorted edges
    __shared__ float4       cob[64];
    __shared__ float        car[64];
    __shared__ u64          keep[64];
    __shared__ unsigned int pref[64];
    __shared__ int          s_last;
    const int tid = threadIdx.x;            // 256 threads

    // ---- tile decode: linear block id -> upper-tri (rb, cb) ----
    {
        int rb = 0, rem = blockIdx.x;
        while (rem >= 64 - rb) { rem -= 64 - rb; rb++; }
        int cb = rb + rem;

        ((float*)cob)[tid] = ((const float*)(g_obox + cb * 64))[tid];
        if (tid < 64) car[tid] = g_area[cb * 64 + tid];
        __syncthreads();

        int r    = tid >> 2;                // 64 rows, 4 threads each
        int row  = rb * 64 + r;
        int kb0  = (tid & 3) * 16;          // 16 cols per thread
        float4 a  = g_obox[row];
        float  aa = g_area[row];
#pragma unroll
        for (int q = 0; q < 16; q++) {
            int k   = kb0 + q;
            int col = cb * 64 + k;
            if (col > row) {
                float4 bbx = cob[k];
                float ltx = fmaxf(a.x, bbx.x), lty = fmaxf(a.y, bbx.y);
                float rbx = fminf(a.z, bbx.z), rby = fminf(a.w, bbx.w);
                float w = fmaxf(__fsub_rn(rbx, ltx), 0.0f);
                float h = fmaxf(__fsub_rn(rby, lty), 0.0f);
                float inter = __fmul_rn(w, h);
                if (inter > 0.0f) {
                    float denom = __fadd_rn(__fsub_rn(__fadd_rn(aa, car[k]), inter), 1e-9f);
                    float iou = __fdiv_rn(inter, denom);
                    if (iou > IOU_T) {
                        unsigned int p = atomicAdd(&g_ecnt, 1u);
                        if (p < ECAP)
                            g_edge[p] = ((unsigned int)row << 12) | (unsigned int)col;
                    }
                }
            }
        }
    }

    // ---- last-block election (threadfenceReduction pattern) ----
    __syncthreads();
    if (tid == 0) {
        __threadfence();
        unsigned int v = atomicAdd(&g_done, 1u);
        s_last = (v == NTILE - 1u);
    }
    __syncthreads();
    if (!s_last) return;

    // ================= final block only =================
    unsigned int E = atomicAdd(&g_ecnt, 0u);
    if (E > ECAP) E = ECAP;
    unsigned int total = g_total;
    if (total > (unsigned)MAX_NMS) total = MAX_NMS;

    if (tid < 64) {
        unsigned int base = tid * 64u;
        u64 w;
        if (total >= base + 64u) w = ~0ULL;
        else if (total <= base)  w = 0ULL;
        else w = (1ULL << (total - base)) - 1ULL;
        keep[tid] = w;
    }
    for (unsigned int i = tid; i < E; i += 256) se[i] = __ldcg(&g_edge[i]);
    __syncthreads();

    // rank-by-count ascending (edges distinct)
    for (unsigned int i = tid; i < E; i += 256) {
        unsigned int mine = se[i];
        unsigned int cnt = 0;
        for (unsigned int j = 0; j < E; j++) cnt += (se[j] < mine);
        se2[cnt] = mine;
    }
    __syncthreads();

    // sequential greedy: ascending src == exact fori_loop semantics
    if (tid == 0) {
        for (unsigned int e = 0; e < E; e++) {
            unsigned int kk = se2[e];
            unsigned int s = kk >> 12, d = kk & 4095u;
            if ((keep[s >> 6] >> (s & 63u)) & 1ULL)
                keep[d >> 6] &= ~(1ULL << (d & 63u));
        }
        unsigned int run = 0;
        for (int w = 0; w < 64; w++) { pref[w] = run; run += __popcll(keep[w]); }
    }
    __syncthreads();

    for (int j = tid; j < MAX_DET * 6; j += 256) out[j] = 0.0f;
    __syncthreads();
    for (int i = tid; i < MAX_NMS; i += 256) {
        u64 wv = keep[i >> 6];
        int b = i & 63;
        if ((wv >> b) & 1ULL) {
            unsigned int rank = pref[i >> 6] +
                (unsigned int)__popcll(wv & ((1ULL << b) - 1ULL));
            if (rank < (unsigned)MAX_DET) {
                float4 bb = g_bbox[i];
                float* o = out + (size_t)rank * 6;
                o[0] = bb.x; o[1] = bb.y; o[2] = bb.z; o[3] = bb.w;
                o[4] = g_score[i]; o[5] = g_clsf[i];
            }
        }
    }

    // ---- reset state for next graph replay (deterministic) ----
    if (tid < NB) g_hist[tid] = 0u;
    if (tid == 0) { g_ecnt = 0u; atomicExch(&g_done, 0u); }
}

// ---------------- launch: 5 nodes ----------------
extern "C" void kernel_launch(void* const* d_in, const int* in_sizes, int n_in,
                              void* d_out, int out_size) {
    const float* pred = (const float*)d_in[0];
    float* out = (float*)d_out;

    k_scores      <<<(N * 32 + 255) / 256, 256>>>(pred);
    k_scan        <<<1, NB>>>();
    k_gather      <<<(N + 255) / 256, 256>>>();
    k_bsort_decode<<<64, 256>>>(pred);
    k_edges_final <<<NTILE, 256>>>(out);
}

// round 13
// speedup vs baseline: 1.2134x; 1.2134x over previous
#include <cuda_runtime.h>
#include <stdint.h>

#define N        100800
#define NC       80
#define STRIDE   85
#define MAX_NMS  4096
#define MAX_DET  1000
#define CAP      16384
#define NB       256
#define SLOT     1024
#define KBASE    0x3ECCu
#define CONF_T   0.4f
#define IOU_T    0.45f
#define MAX_WH   7680.0f
#define ECAP     4096
#define NTILE    2080           // 64*65/2 upper-tri 64x64 tiles

typedef unsigned long long u64;

// ---------------- scratch (static __device__, allocation-free) ----------------
__device__ unsigned int g_hist[NB];       // live counts; zeroed at final tail
__device__ unsigned int g_boff[NB];
__device__ unsigned int g_cutoff, g_total, g_bmax;
__device__ unsigned int g_ecnt = 0;       // zeroed at final tail
__device__ unsigned int g_done = 0;       // last-block election counter
__device__ u64          g_bucket[NB * SLOT];   // 2MB direct-append segments
__device__ u64          g_cand[CAP];
__device__ float4       g_obox[MAX_NMS];
__device__ float        g_area[MAX_NMS];
__device__ float4       g_bbox[MAX_NMS];
__device__ float        g_score[MAX_NMS];
__device__ float        g_clsf[MAX_NMS];
__device__ unsigned int g_edge[ECAP];

// ---------------- K1: warp-per-anchor score + direct bucket append ----------
__global__ void k_scores(const float* __restrict__ pred) {
    int a    = (blockIdx.x * blockDim.x + threadIdx.x) >> 5;
    int lane = threadIdx.x & 31;
    if (a >= N) return;
    const float* r = pred + (size_t)a * STRIDE;
    float v0 = r[lane];                              // obj + cls[0..26]
    float obj = __shfl_sync(0xffffffffu, v0, 4);
    unsigned int key = 0u;
    if (obj > CONF_T) {                              // else conf <= obj <= 0.4
        float v1 = r[lane + 32];
        float v2 = (lane < 21) ? r[lane + 64] : 0.0f;
        float m = 0.0f;
        if (lane >= 5) m = __fmul_rn(v0, obj);
        m = fmaxf(m, __fmul_rn(v1, obj));
        if (lane < 21) m = fmaxf(m, __fmul_rn(v2, obj));
        // all lane values >= 0 -> float bits monotone
        unsigned int mu = __reduce_max_sync(0xffffffffu, __float_as_uint(m));
        if (__uint_as_float(mu) > CONF_T) key = mu;
    }
    if (lane == 0 && key) {
        unsigned int b = (key >> 16) - KBASE;
        if (b > 255u) b = 255u;
        unsigned int pos = atomicAdd(&g_hist[b], 1u);
        if (pos < SLOT)
            g_bucket[b * SLOT + pos] =
                ((u64)key << 32) | (unsigned int)(~(unsigned int)a);
    }
}

// ---------------- K2: 256-bucket suffix scan ----------------
__global__ void k_scan() {
    __shared__ unsigned int s[NB];
    __shared__ int sb;
    int t = threadIdx.x;
    unsigned int h = g_hist[t];
    if (h > SLOT) h = SLOT;                 // clamp (overflow safety)
    g_hist[t] = h;
    s[t] = h;
    if (t == 0) sb = 0;
    __syncthreads();
    for (int off = 1; off < NB; off <<= 1) {
        unsigned int v = (t + off < NB) ? s[t + off] : 0u;
        __syncthreads();
        s[t] += v;
        __syncthreads();
    }
    g_boff[t] = (t < NB - 1) ? s[t + 1] : 0u;   // items strictly above bucket t
    if (s[t] >= (unsigned)MAX_NMS && (t == NB - 1 || s[t + 1] < (unsigned)MAX_NMS)) {
        g_cutoff = (unsigned)t;
        g_total  = s[t];
    }
    if (h) atomicMax(&sb, t);
    __syncthreads();
    if (t == 0) {
        g_bmax = (unsigned)sb;
        if (s[0] < (unsigned)MAX_NMS) { g_cutoff = 0u; g_total = s[0]; }
    }
}

// ---------------- K3: per-bucket rank-by-count -> sorted g_cand ----------
__global__ void k_bsort() {
    __shared__ u64 sbuf[SLOT];          // 8KB
    const int tid = threadIdx.x;        // 256 threads
    unsigned int cutoff = g_cutoff, bmax = g_bmax;
    unsigned int limit = g_total;
    if (limit > (unsigned)MAX_NMS) limit = MAX_NMS;

    for (unsigned int b = cutoff + blockIdx.x; b <= bmax; b += gridDim.x) {
        unsigned int L = g_hist[b];                 // clamped <= SLOT
        if (L == 0) continue;
        unsigned int off = g_boff[b];
        if (off >= limit) continue;
        const u64* seg = g_bucket + (size_t)b * SLOT;
        if (L == 1) {
            if (tid == 0) g_cand[off] = seg[0];
            continue;
        }
        for (unsigned int j = tid; j < L; j += 256) sbuf[j] = seg[j];
        __syncthreads();
        // fixed register slots; keys distinct -> desc rank = #greater
        u64 m0 = ((unsigned)tid        < L) ? sbuf[tid]       : ~0ULL;
        u64 m1 = ((unsigned)tid + 256u < L) ? sbuf[tid + 256] : ~0ULL;
        u64 m2 = ((unsigned)tid + 512u < L) ? sbuf[tid + 512] : ~0ULL;
        u64 m3 = ((unsigned)tid + 768u < L) ? sbuf[tid + 768] : ~0ULL;
        unsigned int c0 = 0, c1 = 0, c2 = 0, c3 = 0;
#pragma unroll 4
        for (unsigned int j = 0; j < L; j++) {
            u64 v = sbuf[j];
            c0 += (v > m0); c1 += (v > m1);
            c2 += (v > m2); c3 += (v > m3);
        }
        if ((unsigned)tid        < L) g_cand[off + c0] = m0;
        if ((unsigned)tid + 256u < L) g_cand[off + c1] = m1;
        if ((unsigned)tid + 512u < L) g_cand[off + c2] = m2;
        if ((unsigned)tid + 768u < L) g_cand[off + c3] = m3;
        __syncthreads();
    }
}

// ---------------- K4: warp-per-rank coalesced decode ----------------
__global__ void k_decode(const float* __restrict__ pred) {
    int r    = (blockIdx.x * blockDim.x + threadIdx.x) >> 5;
    int lane = threadIdx.x & 31;
    unsigned int total = g_total;
    if (total > (unsigned)MAX_NMS) total = MAX_NMS;
    if ((unsigned)r >= total) return;       // rows >= total stay zero forever

    u64 key = g_cand[r];
    unsigned int kb  = (unsigned int)(key >> 32);
    unsigned int idx = ~(unsigned int)(key & 0xFFFFFFFFu);
    float score = __uint_as_float(kb);

    const float* row = pred + (size_t)idx * STRIDE;
    float v0 = row[lane];                   // x y w h obj cls[0..26]
    float v1 = row[lane + 32];              // cls[27..58]
    float v2 = (lane < 21) ? row[lane + 64] : 0.0f;   // cls[59..79]
    float obj = __shfl_sync(0xffffffffu, v0, 4);

    // first class whose product equals the stored max (exact same __fmul_rn)
    unsigned int cand = 0xFFu;
    if (lane >= 5 && __fmul_rn(v0, obj) == score)      cand = (unsigned)(lane - 5);
    else if (__fmul_rn(v1, obj) == score)              cand = (unsigned)(lane + 27);
    else if (lane < 21 && __fmul_rn(v2, obj) == score) cand = (unsigned)(lane + 59);
    unsigned int bestc = __reduce_min_sync(0xffffffffu, cand);

    float x = __shfl_sync(0xffffffffu, v0, 0);
    float y = __shfl_sync(0xffffffffu, v0, 1);
    float w = __shfl_sync(0xffffffffu, v0, 2);
    float h = __shfl_sync(0xffffffffu, v0, 3);

    if (lane == 0) {
        float hw = __fmul_rn(w, 0.5f), hh = __fmul_rn(h, 0.5f);
        float x1 = __fsub_rn(x, hw), y1 = __fsub_rn(y, hh);
        float x2 = __fadd_rn(x, hw), y2 = __fadd_rn(y, hh);
        float cf = (float)bestc;
        float off = __fmul_rn(cf, MAX_WH);
        float ox1 = __fadd_rn(x1, off), oy1 = __fadd_rn(y1, off);
        float ox2 = __fadd_rn(x2, off), oy2 = __fadd_rn(y2, off);
        float area = __fmul_rn(__fsub_rn(ox2, ox1), __fsub_rn(oy2, oy1));
        g_obox[r]  = make_float4(ox1, oy1, ox2, oy2);
        g_area[r]  = area;
        g_bbox[r]  = make_float4(x1, y1, x2, y2);
        g_score[r] = score;
        g_clsf[r]  = cf;
    }
}

// ---------------- K5: edges + (last block) greedy + emit + state reset -------
__global__ void k_edges_final(float* __restrict__ out) {
    __shared__ unsigned int se[4096];       // raw edges
    __shared__ unsigned int se2[4096];      // rank-sorted edges
    __shared__ float4       cob[64];
    __shared__ float        car[64];
    __shared__ u64          keep[64];
    __shared__ unsigned int pref[64];
    __shared__ int          s_last;
    const int tid = threadIdx.x;            // 256 threads

    // ---- tile decode: linear block id -> upper-tri (rb, cb) ----
    {
        int rb = 0, rem = blockIdx.x;
        while (rem >= 64 - rb) { rem -= 64 - rb; rb++; }
        int cb = rb + rem;

        ((float*)cob)[tid] = ((const float*)(g_obox + cb * 64))[tid];
        if (tid < 64) car[tid] = g_area[cb * 64 + tid];
        __syncthreads();

        int r    = tid >> 2;                // 64 rows, 4 threads each
        int row  = rb * 64 + r;
        int kb0  = (tid & 3) * 16;          // 16 cols per thread
        float4 a  = g_obox[row];
        float  aa = g_area[row];
#pragma unroll
        for (int q = 0; q < 16; q++) {
            int k   = kb0 + q;
            int col = cb * 64 + k;
            if (col > row) {
                float4 bbx = cob[k];
                float ltx = fmaxf(a.x, bbx.x), lty = fmaxf(a.y, bbx.y);
                float rbx = fminf(a.z, bbx.z), rby = fminf(a.w, bbx.w);
                float w = fmaxf(__fsub_rn(rbx, ltx), 0.0f);
                float h = fmaxf(__fsub_rn(rby, lty), 0.0f);
                float inter = __fmul_rn(w, h);
                if (inter > 0.0f) {
                    float denom = __fadd_rn(__fsub_rn(__fadd_rn(aa, car[k]), inter), 1e-9f);
                    float iou = __fdiv_rn(inter, denom);
                    if (iou > IOU_T) {
                        unsigned int p = atomicAdd(&g_ecnt, 1u);
                        if (p < ECAP)
                            g_edge[p] = ((unsigned int)row << 12) | (unsigned int)col;
                    }
                }
            }
        }
    }

    // ---- last-block election (threadfenceReduction pattern) ----
    __syncthreads();
    if (tid == 0) {
        __threadfence();
        unsigned int v = atomicAdd(&g_done, 1u);
        s_last = (v == NTILE - 1u);
    }
    __syncthreads();
    if (!s_last) return;

    // ================= final block only =================
    unsigned int E = atomicAdd(&g_ecnt, 0u);
    if (E > ECAP) E = ECAP;
    unsigned int total = g_total;
    if (total > (unsigned)MAX_NMS) total = MAX_NMS;

    if (tid < 64) {
        unsigned int base = tid * 64u;
        u64 w;
        if (total >= base + 64u) w = ~0ULL;
        else if (total <= base)  w = 0ULL;
        else w = (1ULL << (total - base)) - 1ULL;
        keep[tid] = w;
    }
    for (unsigned int i = tid; i < E; i += 256) se[i] = __ldcg(&g_edge[i]);
    __syncthreads();

    // rank-by-count ascending (edges distinct)
    for (unsigned int i = tid; i < E; i += 256) {
        unsigned int mine = se[i];
        unsigned int cnt = 0;
        for (unsigned int j = 0; j < E; j++) cnt += (se[j] < mine);
        se2[cnt] = mine;
    }
    __syncthreads();

    // sequential greedy: ascending src == exact fori_loop semantics
    if (tid == 0) {
        for (unsigned int e = 0; e < E; e++) {
            unsigned int kk = se2[e];
            unsigned int s = kk >> 12, d = kk & 4095u;
            if ((keep[s >> 6] >> (s & 63u)) & 1ULL)
                keep[d >> 6] &= ~(1ULL << (d & 63u));
        }
        unsigned int run = 0;
        for (int w = 0; w < 64; w++) { pref[w] = run; run += __popcll(keep[w]); }
    }
    __syncthreads();

    for (int j = tid; j < MAX_DET * 6; j += 256) out[j] = 0.0f;
    __syncthreads();
    for (int i = tid; i < MAX_NMS; i += 256) {
        u64 wv = keep[i >> 6];
        int b = i & 63;
        if ((wv >> b) & 1ULL) {
            unsigned int rank = pref[i >> 6] +
                (unsigned int)__popcll(wv & ((1ULL << b) - 1ULL));
            if (rank < (unsigned)MAX_DET) {
                float4 bb = g_bbox[i];
                float* o = out + (size_t)rank * 6;
                o[0] = bb.x; o[1] = bb.y; o[2] = bb.z; o[3] = bb.w;
                o[4] = g_score[i]; o[5] = g_clsf[i];
            }
        }
    }

    // ---- reset state for next graph replay (deterministic) ----
    if (tid < NB) g_hist[tid] = 0u;
    if (tid == 0) { g_ecnt = 0u; atomicExch(&g_done, 0u); }
}

// ---------------- launch: 5 nodes ----------------
extern "C" void kernel_launch(void* const* d_in, const int* in_sizes, int n_in,
                              void* d_out, int out_size) {
    const float* pred = (const float*)d_in[0];
    float* out = (float*)d_out;

    k_scores     <<<(N * 32 + 255) / 256, 256>>>(pred);
    k_scan       <<<1, NB>>>();
    k_bsort      <<<64, 256>>>();
    k_decode     <<<(MAX_NMS * 32) / 256, 256>>>(pred);
    k_edges_final<<<NTILE, 256>>>(out);
}

// round 14
// speedup vs baseline: 1.4250x; 1.1744x over previous
#include <cuda_runtime.h>
#include <stdint.h>

#define N        100800
#define NC       80
#define STRIDE   85
#define MAX_NMS  4096
#define MAX_DET  1000
#define CAP      16384
#define NB       256
#define SLOT     1024
#define KBASE    0x3ECCu
#define CONF_T   0.4f
#define IOU_T    0.45f
#define MAX_WH   7680.0f
#define ECAP     4096
#define CCAP     256            // per-class rank list cap (expected max ~85)

typedef unsigned long long u64;

// ---------------- scratch (static __device__, allocation-free) ----------------
__device__ unsigned int g_hist[NB];       // live counts; zeroed at final tail
__device__ unsigned int g_boff[NB];
__device__ unsigned int g_cutoff, g_total, g_bmax;
__device__ unsigned int g_ecnt = 0;       // zeroed at final tail
__device__ unsigned int g_done = 0;       // last-block election counter
__device__ unsigned int g_ccnt[NC];       // per-class counts; zeroed at tail
__device__ unsigned int g_cls[NC * CCAP]; // per-class rank lists
__device__ u64          g_bucket[NB * SLOT];   // 2MB direct-append segments
__device__ u64          g_cand[CAP];
__device__ float4       g_obox[MAX_NMS];
__device__ float        g_area[MAX_NMS];
__device__ float4       g_bbox[MAX_NMS];
__device__ float        g_score[MAX_NMS];
__device__ float        g_clsf[MAX_NMS];
__device__ unsigned int g_edge[ECAP];

// ---------------- K1: warp-per-anchor score + direct bucket append ----------
__global__ void k_scores(const float* __restrict__ pred) {
    int a    = (blockIdx.x * blockDim.x + threadIdx.x) >> 5;
    int lane = threadIdx.x & 31;
    if (a >= N) return;
    const float* r = pred + (size_t)a * STRIDE;
    float v0 = r[lane];                              // x y w h obj cls[0..26]
    float obj = __shfl_sync(0xffffffffu, v0, 4);
    unsigned int key = 0u;
    if (obj > CONF_T) {                              // else conf <= obj <= 0.4
        float v1 = r[lane + 32];
        float v2 = (lane < 21) ? r[lane + 64] : 0.0f;
        float m = 0.0f;
        if (lane >= 5) m = __fmul_rn(v0, obj);
        m = fmaxf(m, __fmul_rn(v1, obj));
        if (lane < 21) m = fmaxf(m, __fmul_rn(v2, obj));
        // all lane values >= 0 -> float bits monotone
        unsigned int mu = __reduce_max_sync(0xffffffffu, __float_as_uint(m));
        if (__uint_as_float(mu) > CONF_T) key = mu;
    }
    if (lane == 0 && key) {
        unsigned int b = (key >> 16) - KBASE;
        if (b > 255u) b = 255u;
        unsigned int pos = atomicAdd(&g_hist[b], 1u);
        if (pos < SLOT)
            g_bucket[b * SLOT + pos] =
                ((u64)key << 32) | (unsigned int)(~(unsigned int)a);
    }
}

// ---------------- K2: 256-bucket suffix scan ----------------
__global__ void k_scan() {
    __shared__ unsigned int s[NB];
    __shared__ int sb;
    int t = threadIdx.x;
    unsigned int h = g_hist[t];
    if (h > SLOT) h = SLOT;                 // clamp (overflow safety)
    g_hist[t] = h;
    s[t] = h;
    if (t == 0) sb = 0;
    __syncthreads();
    for (int off = 1; off < NB; off <<= 1) {
        unsigned int v = (t + off < NB) ? s[t + off] : 0u;
        __syncthreads();
        s[t] += v;
        __syncthreads();
    }
    g_boff[t] = (t < NB - 1) ? s[t + 1] : 0u;   // items strictly above bucket t
    if (s[t] >= (unsigned)MAX_NMS && (t == NB - 1 || s[t + 1] < (unsigned)MAX_NMS)) {
        g_cutoff = (unsigned)t;
        g_total  = s[t];
    }
    if (h) atomicMax(&sb, t);
    __syncthreads();
    if (t == 0) {
        g_bmax = (unsigned)sb;
        if (s[0] < (unsigned)MAX_NMS) { g_cutoff = 0u; g_total = s[0]; }
    }
}

// ---------------- K3: per-bucket rank-by-count -> sorted g_cand ----------
__global__ void k_bsort() {
    __shared__ u64 sbuf[SLOT];          // 8KB
    const int tid = threadIdx.x;        // 256 threads
    unsigned int cutoff = g_cutoff, bmax = g_bmax;
    unsigned int limit = g_total;
    if (limit > (unsigned)MAX_NMS) limit = MAX_NMS;

    for (unsigned int b = cutoff + blockIdx.x; b <= bmax; b += gridDim.x) {
        unsigned int L = g_hist[b];                 // clamped <= SLOT
        if (L == 0) continue;
        unsigned int off = g_boff[b];
        if (off >= limit) continue;
        const u64* seg = g_bucket + (size_t)b * SLOT;
        if (L == 1) {
            if (tid == 0) g_cand[off] = seg[0];
            continue;
        }
        for (unsigned int j = tid; j < L; j += 256) sbuf[j] = seg[j];
        __syncthreads();
        // fixed register slots; keys distinct -> desc rank = #greater
        u64 m0 = ((unsigned)tid        < L) ? sbuf[tid]       : ~0ULL;
        u64 m1 = ((unsigned)tid + 256u < L) ? sbuf[tid + 256] : ~0ULL;
        u64 m2 = ((unsigned)tid + 512u < L) ? sbuf[tid + 512] : ~0ULL;
        u64 m3 = ((unsigned)tid + 768u < L) ? sbuf[tid + 768] : ~0ULL;
        unsigned int c0 = 0, c1 = 0, c2 = 0, c3 = 0;
#pragma unroll 4
        for (unsigned int j = 0; j < L; j++) {
            u64 v = sbuf[j];
            c0 += (v > m0); c1 += (v > m1);
            c2 += (v > m2); c3 += (v > m3);
        }
        if ((unsigned)tid        < L) g_cand[off + c0] = m0;
        if ((unsigned)tid + 256u < L) g_cand[off + c1] = m1;
        if ((unsigned)tid + 512u < L) g_cand[off + c2] = m2;
        if ((unsigned)tid + 768u < L) g_cand[off + c3] = m3;
        __syncthreads();
    }
}

// ---------------- K4: warp-per-rank coalesced decode + class binning --------
__global__ void k_decode(const float* __restrict__ pred) {
    int r    = (blockIdx.x * blockDim.x + threadIdx.x) >> 5;
    int lane = threadIdx.x & 31;
    unsigned int total = g_total;
    if (total > (unsigned)MAX_NMS) total = MAX_NMS;
    if ((unsigned)r >= total) return;       // rows >= total stay zero forever

    u64 key = g_cand[r];
    unsigned int kb  = (unsigned int)(key >> 32);
    unsigned int idx = ~(unsigned int)(key & 0xFFFFFFFFu);
    float score = __uint_as_float(kb);

    const float* row = pred + (size_t)idx * STRIDE;
    float v0 = row[lane];                   // x y w h obj cls[0..26]
    float v1 = row[lane + 32];              // cls[27..58]
    float v2 = (lane < 21) ? row[lane + 64] : 0.0f;   // cls[59..79]
    float obj = __shfl_sync(0xffffffffu, v0, 4);

    // first class whose product equals the stored max (exact same __fmul_rn)
    unsigned int cand = 0xFFu;
    if (lane >= 5 && __fmul_rn(v0, obj) == score)      cand = (unsigned)(lane - 5);
    else if (__fmul_rn(v1, obj) == score)              cand = (unsigned)(lane + 27);
    else if (lane < 21 && __fmul_rn(v2, obj) == score) cand = (unsigned)(lane + 59);
    unsigned int bestc = __reduce_min_sync(0xffffffffu, cand);

    float x = __shfl_sync(0xffffffffu, v0, 0);
    float y = __shfl_sync(0xffffffffu, v0, 1);
    float w = __shfl_sync(0xffffffffu, v0, 2);
    float h = __shfl_sync(0xffffffffu, v0, 3);

    if (lane == 0) {
        float hw = __fmul_rn(w, 0.5f), hh = __fmul_rn(h, 0.5f);
        float x1 = __fsub_rn(x, hw), y1 = __fsub_rn(y, hh);
        float x2 = __fadd_rn(x, hw), y2 = __fadd_rn(y, hh);
        float cf = (float)bestc;
        float off = __fmul_rn(cf, MAX_WH);
        float ox1 = __fadd_rn(x1, off), oy1 = __fadd_rn(y1, off);
        float ox2 = __fadd_rn(x2, off), oy2 = __fadd_rn(y2, off);
        float area = __fmul_rn(__fsub_rn(ox2, ox1), __fsub_rn(oy2, oy1));
        g_obox[r]  = make_float4(ox1, oy1, ox2, oy2);
        g_area[r]  = area;
        g_bbox[r]  = make_float4(x1, y1, x2, y2);
        g_score[r] = score;
        g_clsf[r]  = cf;
        // class bin: only same-class pairs can ever have inter > 0
        unsigned int p = atomicAdd(&g_ccnt[bestc], 1u);
        if (p < CCAP) g_cls[bestc * CCAP + p] = (unsigned int)r;
    }
}

// ---------------- K5: per-class all-pairs edges + (last block) final --------
__global__ void k_cedges_final(float* __restrict__ out) {
    __shared__ union {
        struct { float4 sob[CCAP]; float sar[CCAP]; unsigned int sr[CCAP]; } a; // 6KB
        struct { unsigned int se[4096]; unsigned int se2[4096]; } b;            // 32KB
    } U;
    __shared__ u64          keep[64];
    __shared__ unsigned int pref[64];
    __shared__ int          s_last;
    const int tid = threadIdx.x;            // 256 threads; grid = NC blocks

    // ---- per-class all-pairs IoU (identical arithmetic; symmetric in FP) ----
    {
        int c = blockIdx.x;
        unsigned int nc = g_ccnt[c];
        if (nc > CCAP) nc = CCAP;
        for (unsigned int i = tid; i < nc; i += 256) {
            unsigned int r = g_cls[c * CCAP + i];
            U.a.sr[i]  = r;
            U.a.sob[i] = g_obox[r];
            U.a.sar[i] = g_area[r];
        }
        __syncthreads();
        unsigned int np = nc * nc;
        for (unsigned int p = tid; p < np; p += 256) {
            unsigned int i = p / nc, j = p - i * nc;
            if (j <= i) continue;
            float4 A = U.a.sob[i], B = U.a.sob[j];
            float ltx = fmaxf(A.x, B.x), lty = fmaxf(A.y, B.y);
            float rbx = fminf(A.z, B.z), rby = fminf(A.w, B.w);
            float w = fmaxf(__fsub_rn(rbx, ltx), 0.0f);
            float h = fmaxf(__fsub_rn(rby, lty), 0.0f);
            float inter = __fmul_rn(w, h);
            if (inter > 0.0f) {
                float denom = __fadd_rn(
                    __fsub_rn(__fadd_rn(U.a.sar[i], U.a.sar[j]), inter), 1e-9f);
                float iou = __fdiv_rn(inter, denom);
                if (iou > IOU_T) {
                    unsigned int ri = U.a.sr[i], rj = U.a.sr[j];
                    unsigned int s = ri < rj ? ri : rj;
                    unsigned int d = ri < rj ? rj : ri;
                    unsigned int e = atomicAdd(&g_ecnt, 1u);
                    if (e < ECAP)
                        g_edge[e] = (s << 12) | d;
                }
            }
        }
    }

    // ---- last-block election (threadfenceReduction pattern) ----
    __syncthreads();
    if (tid == 0) {
        __threadfence();
        unsigned int v = atomicAdd(&g_done, 1u);
        s_last = (v == (unsigned)NC - 1u);
    }
    __syncthreads();
    if (!s_last) return;

    // ================= final block only =================
    unsigned int E = atomicAdd(&g_ecnt, 0u);
    if (E > ECAP) E = ECAP;
    unsigned int total = g_total;
    if (total > (unsigned)MAX_NMS) total = MAX_NMS;

    if (tid < 64) {
        unsigned int base = tid * 64u;
        u64 w;
        if (total >= base + 64u) w = ~0ULL;
        else if (total <= base)  w = 0ULL;
        else w = (1ULL << (total - base)) - 1ULL;
        keep[tid] = w;
    }
    __syncthreads();                         // union phase switch (a -> b)
    for (unsigned int i = tid; i < E; i += 256) U.b.se[i] = __ldcg(&g_edge[i]);
    __syncthreads();

    // rank-by-count ascending (edges distinct)
    for (unsigned int i = tid; i < E; i += 256) {
        unsigned int mine = U.b.se[i];
        unsigned int cnt = 0;
        for (unsigned int j = 0; j < E; j++) cnt += (U.b.se[j] < mine);
        U.b.se2[cnt] = mine;
    }
    __syncthreads();

    // sequential greedy: ascending src == exact fori_loop semantics
    if (tid == 0) {
        for (unsigned int e = 0; e < E; e++) {
            unsigned int kk = U.b.se2[e];
            unsigned int s = kk >> 12, d = kk & 4095u;
            if ((keep[s >> 6] >> (s & 63u)) & 1ULL)
                keep[d >> 6] &= ~(1ULL << (d & 63u));
        }
        unsigned int run = 0;
        for (int w = 0; w < 64; w++) { pref[w] = run; run += __popcll(keep[w]); }
    }
    __syncthreads();

    for (int j = tid; j < MAX_DET * 6; j += 256) out[j] = 0.0f;
    __syncthreads();
    for (int i = tid; i < MAX_NMS; i += 256) {
        u64 wv = keep[i >> 6];
        int b = i & 63;
        if ((wv >> b) & 1ULL) {
            unsigned int rank = pref[i >> 6] +
                (unsigned int)__popcll(wv & ((1ULL << b) - 1ULL));
            if (rank < (unsigned)MAX_DET) {
                float4 bb = g_bbox[i];
                float* o = out + (size_t)rank * 6;
                o[0] = bb.x; o[1] = bb.y; o[2] = bb.z; o[3] = bb.w;
                o[4] = g_score[i]; o[5] = g_clsf[i];
            }
        }
    }

    // ---- reset state for next graph replay (deterministic) ----
    if (tid < NB) g_hist[tid] = 0u;
    if (tid < NC) g_ccnt[tid] = 0u;
    if (tid == 0) { g_ecnt = 0u; atomicExch(&g_done, 0u); }
}

// ---------------- launch: 5 nodes ----------------
extern "C" void kernel_launch(void* const* d_in, const int* in_sizes, int n_in,
                              void* d_out, int out_size) {
    const float* pred = (const float*)d_in[0];
    float* out = (float*)d_out;

    k_scores      <<<(N * 32 + 255) / 256, 256>>>(pred);
    k_scan        <<<1, NB>>>();
    k_bsort       <<<64, 256>>>();
    k_decode      <<<(MAX_NMS * 32) / 256, 256>>>(pred);
    k_cedges_final<<<NC, 256>>>(out);
}